// round 9
// baseline (speedup 1.0000x reference)
#include <cuda_runtime.h>
#include <cuda_bf16.h>
#include <cstdint>

#define BB 4
#define HH 16
#define SSEQ 2048
#define DDIM 64
#define NHEAD (BB * HH)
#define STRD 72          // bf16 per SMEM operand row (k=64 + pad, conflict-free)
#define UNIF (1.0f / 2048.0f)

// ---------------- mma.sync m16n8k16 bf16 (family-portable) -------------------
__device__ __forceinline__ void mma_bf16(float* c, const uint32_t* a, const uint32_t* b) {
    asm volatile(
        "mma.sync.aligned.m16n8k16.row.col.f32.bf16.bf16.f32 "
        "{%0,%1,%2,%3}, {%4,%5,%6,%7}, {%8,%9}, {%0,%1,%2,%3};"
        : "+f"(c[0]), "+f"(c[1]), "+f"(c[2]), "+f"(c[3])
        : "r"(a[0]), "r"(a[1]), "r"(a[2]), "r"(a[3]), "r"(b[0]), "r"(b[1]));
}

__device__ __forceinline__ void split2(float x, float y, uint32_t& h, uint32_t& l) {
    __nv_bfloat162 hh = __floats2bfloat162_rn(x, y);
    const float hx = __bfloat162float(__low2bfloat16(hh));
    const float hy = __bfloat162float(__high2bfloat16(hh));
    __nv_bfloat162 ll = __floats2bfloat162_rn(x - hx, y - hy);
    h = *(uint32_t*)&hh;
    l = *(uint32_t*)&ll;
}
__device__ __forceinline__ uint32_t packhi2(float x, float y) {
    __nv_bfloat162 t = __floats2bfloat162_rn(x, y);
    return *(uint32_t*)&t;
}
__device__ __forceinline__ uint32_t packlo2(float x, float y) {
    __nv_bfloat162 h = __floats2bfloat162_rn(x, y);
    const float hx = __bfloat162float(__low2bfloat16(h));
    const float hy = __bfloat162float(__high2bfloat16(h));
    __nv_bfloat162 l = __floats2bfloat162_rn(x - hx, y - hy);
    return *(uint32_t*)&l;
}

// scratch for output-variant cases
__device__ float g_wscratch[(size_t)NHEAD * SSEQ * SSEQ];
__device__ float g_oscratch[(size_t)NHEAD * SSEQ * DDIM];

// SMEM layout (bytes)
#define OFF_QH   0
#define OFF_QL   (OFF_QH + 128 * STRD * 2)
#define OFF_KH   (OFF_QL + 128 * STRD * 2)
#define OFF_KL   (OFF_KH + 64 * STRD * 2)
#define OFF_VH   (OFF_KL + 64 * STRD * 2)
#define OFF_VL   (OFF_VH + 64 * STRD * 2)
#define OFF_VRAW (OFF_VL + 64 * STRD * 2)
#define OFF_SUM  (OFF_VRAW + 64 * 67 * 4)
#define OFF_PAD  (OFF_SUM + 128 * 4)
#define SMEM_BYTES (OFF_PAD + 64 * 4)       // 91648

// QK^T for one 64-col chunk: 3-pass bf16 split, warp tile 16(m) x 64(n)
__device__ __forceinline__ void qk_3pass(float acc[8][4],
                                         const uint16_t* sQh, const uint16_t* sQl,
                                         const uint16_t* sKh, const uint16_t* sKl,
                                         int mrow, int g, int tq)
{
    #pragma unroll
    for (int nf = 0; nf < 8; ++nf)
        #pragma unroll
        for (int j = 0; j < 4; ++j) acc[nf][j] = 0.f;

    #pragma unroll
    for (int pass = 0; pass < 3; ++pass) {
        const uint16_t* A = (pass == 2) ? sQl : sQh;
        const uint16_t* B = (pass == 1) ? sKl : sKh;
        #pragma unroll
        for (int ks = 0; ks < 4; ++ks) {
            const int k0 = ks * 16;
            const uint16_t* ap = A + (mrow + g) * STRD + k0 + 2 * tq;
            uint32_t af[4];
            af[0] = *(const uint32_t*)ap;
            af[1] = *(const uint32_t*)(ap + 8 * STRD);
            af[2] = *(const uint32_t*)(ap + 8);
            af[3] = *(const uint32_t*)(ap + 8 * STRD + 8);
            #pragma unroll
            for (int nf = 0; nf < 8; ++nf) {
                const uint16_t* bp = B + (nf * 8 + g) * STRD + k0 + 2 * tq;
                uint32_t bf[2];
                bf[0] = *(const uint32_t*)bp;
                bf[1] = *(const uint32_t*)(bp + 8);
                mma_bf16(acc[nf], af, bf);
            }
        }
    }
}

__global__ void __launch_bounds__(256, 2)
fused_attn(const float* __restrict__ Q, const float* __restrict__ K,
           const float* __restrict__ V, const int* __restrict__ pad,
           float* __restrict__ W, float* __restrict__ O)
{
    extern __shared__ char smem[];
    uint16_t* sQh = (uint16_t*)(smem + OFF_QH);
    uint16_t* sQl = (uint16_t*)(smem + OFF_QL);
    uint16_t* sKh = (uint16_t*)(smem + OFF_KH);
    uint16_t* sKl = (uint16_t*)(smem + OFF_KL);
    uint16_t* sVh = (uint16_t*)(smem + OFF_VH);
    uint16_t* sVl = (uint16_t*)(smem + OFF_VL);
    float*    vraw = (float*)(smem + OFF_VRAW);
    float*    ssum = (float*)(smem + OFF_SUM);
    int*      spad = (int*)(smem + OFF_PAD);

    const int tid = threadIdx.x;
    const int wid = tid >> 5, lane = tid & 31;
    const int g = lane >> 2, tq = lane & 3;
    const int head = blockIdx.y;
    const int q0 = blockIdx.x * 128;
    const int b = head >> 4;
    const int mrow = wid * 16;
    const int r0 = mrow + g, r1 = r0 + 8;
    const int qg0 = q0 + r0, qg1 = q0 + r1;

    // ---- stage Q once (x0.125, hi/lo split) ----
    const float4* Qg = (const float4*)(Q + ((size_t)head * SSEQ + q0) * DDIM);
    for (int i = tid; i < 128 * 16; i += 256) {
        const int r = i >> 4, c4 = i & 15;
        float4 v = Qg[i];
        v.x *= 0.125f; v.y *= 0.125f; v.z *= 0.125f; v.w *= 0.125f;
        uint32_t h0, l0, h1, l1;
        split2(v.x, v.y, h0, l0); split2(v.z, v.w, h1, l1);
        uint32_t* dh = (uint32_t*)(sQh + r * STRD + c4 * 4);
        uint32_t* dl = (uint32_t*)(sQl + r * STRD + c4 * 4);
        dh[0] = h0; dh[1] = h1; dl[0] = l0; dl[1] = l1;
    }
    if (tid < 128) ssum[tid] = 0.f;

    const float4* Kg4 = (const float4*)(K + (size_t)head * SSEQ * DDIM);
    const float4* Vg4 = (const float4*)(V + (size_t)head * SSEQ * DDIM);

    // ================= Phase 1: row sums of exp(s) (m = 0) =================
    for (int t = 0; t < 32; ++t) {
        const int c0 = t * 64;
        __syncthreads();
        for (int i = tid; i < 64 * 16; i += 256) {
            const int r = i >> 4, c4 = i & 15;
            const float4 k = Kg4[(size_t)c0 * 16 + i];
            uint32_t h0, l0, h1, l1;
            split2(k.x, k.y, h0, l0); split2(k.z, k.w, h1, l1);
            uint32_t* dh = (uint32_t*)(sKh + r * STRD + c4 * 4);
            uint32_t* dl = (uint32_t*)(sKl + r * STRD + c4 * 4);
            dh[0] = h0; dh[1] = h1; dl[0] = l0; dl[1] = l1;
        }
        if (tid < 64) spad[tid] = pad[b * SSEQ + c0 + tid];
        __syncthreads();

        float acc[8][4];
        qk_3pass(acc, sQh, sQl, sKh, sKl, mrow, g, tq);

        float rs0 = 0.f, rs1 = 0.f;
        #pragma unroll
        for (int nf = 0; nf < 8; ++nf) {
            const int c = nf * 8 + 2 * tq;
            const int cg = c0 + c;
            const int p0 = spad[c], p1 = spad[c + 1];
            rs0 += (((cg     > qg0 ? 1 : 0) + p0) == 1) ? 0.f : __expf(acc[nf][0]);
            rs0 += (((cg + 1 > qg0 ? 1 : 0) + p1) == 1) ? 0.f : __expf(acc[nf][1]);
            rs1 += (((cg     > qg1 ? 1 : 0) + p0) == 1) ? 0.f : __expf(acc[nf][2]);
            rs1 += (((cg + 1 > qg1 ? 1 : 0) + p1) == 1) ? 0.f : __expf(acc[nf][3]);
        }
        rs0 += __shfl_xor_sync(0xffffffffu, rs0, 1);
        rs0 += __shfl_xor_sync(0xffffffffu, rs0, 2);
        rs1 += __shfl_xor_sync(0xffffffffu, rs1, 1);
        rs1 += __shfl_xor_sync(0xffffffffu, rs1, 2);
        if (tq == 0) { ssum[r0] += rs0; ssum[r1] += rs1; }
    }
    __syncthreads();
    if (tid < 128) {
        const float s = ssum[tid];
        ssum[tid] = (s == 0.f) ? -1.f : 1.f / s;   // -1 sentinel: all-masked row
    }
    __syncthreads();
    const float inv0 = ssum[r0], inv1 = ssum[r1];
    const bool uni0 = inv0 < 0.f, uni1 = inv1 < 0.f;

    // ================= Phase 2: recompute, write W, accumulate O ===========
    float oacc[8][4];
    #pragma unroll
    for (int nf = 0; nf < 8; ++nf)
        #pragma unroll
        for (int j = 0; j < 4; ++j) oacc[nf][j] = 0.f;

    for (int t = 0; t < 32; ++t) {
        const int c0 = t * 64;
        __syncthreads();
        for (int i = tid; i < 64 * 16; i += 256) {
            const int r = i >> 4, c4 = i & 15;
            const float4 k = Kg4[(size_t)c0 * 16 + i];
            uint32_t h0, l0, h1, l1;
            split2(k.x, k.y, h0, l0); split2(k.z, k.w, h1, l1);
            uint32_t* dh = (uint32_t*)(sKh + r * STRD + c4 * 4);
            uint32_t* dl = (uint32_t*)(sKl + r * STRD + c4 * 4);
            dh[0] = h0; dh[1] = h1; dl[0] = l0; dl[1] = l1;
            const float4 v = Vg4[(size_t)c0 * 16 + i];
            float* d = vraw + r * 67 + c4 * 4;
            d[0] = v.x; d[1] = v.y; d[2] = v.z; d[3] = v.w;
        }
        if (tid < 64) spad[tid] = pad[b * SSEQ + c0 + tid];
        __syncthreads();

        // transpose V -> [d][s] hi/lo (stride-67 reads conflict-free)
        {
            const int s = tid & 63, dg = tid >> 6;
            #pragma unroll
            for (int j = 0; j < 16; ++j) {
                const int d = dg * 16 + j;
                const float v = vraw[s * 67 + d];
                const __nv_bfloat16 bh = __float2bfloat16(v);
                const float fh = __bfloat162float(bh);
                sVh[d * STRD + s] = __bfloat16_as_ushort(bh);
                sVl[d * STRD + s] = __bfloat16_as_ushort(__float2bfloat16(v - fh));
            }
        }

        float acc[8][4];
        qk_3pass(acc, sQh, sQl, sKh, sKl, mrow, g, tq);   // bitwise == phase 1
        __syncthreads();   // V^T ready for all warps

        // p = exp(s) * inv (or uniform / 0), write W once
        float* wr0 = W + ((size_t)head * SSEQ + qg0) * SSEQ + c0;
        float* wr1 = W + ((size_t)head * SSEQ + qg1) * SSEQ + c0;
        #pragma unroll
        for (int nf = 0; nf < 8; ++nf) {
            const int c = nf * 8 + 2 * tq;
            const int cg = c0 + c;
            const int p0 = spad[c], p1 = spad[c + 1];
            float v0 = uni0 ? UNIF : ((((cg     > qg0 ? 1 : 0) + p0) == 1) ? 0.f : __expf(acc[nf][0]) * inv0);
            float v1 = uni0 ? UNIF : ((((cg + 1 > qg0 ? 1 : 0) + p1) == 1) ? 0.f : __expf(acc[nf][1]) * inv0);
            float v2 = uni1 ? UNIF : ((((cg     > qg1 ? 1 : 0) + p0) == 1) ? 0.f : __expf(acc[nf][2]) * inv1);
            float v3 = uni1 ? UNIF : ((((cg + 1 > qg1 ? 1 : 0) + p1) == 1) ? 0.f : __expf(acc[nf][3]) * inv1);
            acc[nf][0] = v0; acc[nf][1] = v1; acc[nf][2] = v2; acc[nf][3] = v3;
            __stcs((float2*)(wr0 + c), make_float2(v0, v1));
            __stcs((float2*)(wr1 + c), make_float2(v2, v3));
        }

        // P@V: A fragments straight from p registers (C layout == A layout)
        #pragma unroll
        for (int pass = 0; pass < 3; ++pass) {
            const uint16_t* Bb = (pass == 1) ? sVl : sVh;
            #pragma unroll
            for (int j = 0; j < 4; ++j) {
                uint32_t a[4];
                if (pass < 2) {
                    a[0] = packhi2(acc[2*j][0],   acc[2*j][1]);
                    a[1] = packhi2(acc[2*j][2],   acc[2*j][3]);
                    a[2] = packhi2(acc[2*j+1][0], acc[2*j+1][1]);
                    a[3] = packhi2(acc[2*j+1][2], acc[2*j+1][3]);
                } else {
                    a[0] = packlo2(acc[2*j][0],   acc[2*j][1]);
                    a[1] = packlo2(acc[2*j][2],   acc[2*j][3]);
                    a[2] = packlo2(acc[2*j+1][0], acc[2*j+1][1]);
                    a[3] = packlo2(acc[2*j+1][2], acc[2*j+1][3]);
                }
                #pragma unroll
                for (int nf2 = 0; nf2 < 8; ++nf2) {
                    const uint16_t* bp = Bb + (nf2 * 8 + g) * STRD + j * 16 + 2 * tq;
                    uint32_t bf[2];
                    bf[0] = *(const uint32_t*)bp;
                    bf[1] = *(const uint32_t*)(bp + 8);
                    mma_bf16(oacc[nf2], a, bf);
                }
            }
        }
    }

    // ---- O epilogue ----
    float* o0 = O + ((size_t)head * SSEQ + qg0) * DDIM;
    float* o1 = O + ((size_t)head * SSEQ + qg1) * DDIM;
    #pragma unroll
    for (int nf2 = 0; nf2 < 8; ++nf2) {
        const int c = nf2 * 8 + 2 * tq;
        *(float2*)(o0 + c) = make_float2(oacc[nf2][0], oacc[nf2][1]);
        *(float2*)(o1 + c) = make_float2(oacc[nf2][2], oacc[nf2][3]);
    }
}

// ===================== launch =================================================
extern "C" void kernel_launch(void* const* d_in, const int* in_sizes, int n_in,
                              void* d_out, int out_size)
{
    const float* Q   = (const float*)d_in[0];
    const float* K   = (const float*)d_in[1];
    const float* V   = (const float*)d_in[2];
    const int*   pad = (const int*)d_in[3];

    const long long RES_N = (long long)NHEAD * SSEQ * DDIM;
    const long long W_N   = (long long)NHEAD * SSEQ * (long long)SSEQ;

    float* o = (float*)d_out;
    float* out_res = nullptr;
    float* out_w   = nullptr;
    if ((long long)out_size == RES_N) {
        out_res = o;
        cudaGetSymbolAddress((void**)&out_w, g_wscratch);
    } else if ((long long)out_size == W_N) {
        out_w = o;
        cudaGetSymbolAddress((void**)&out_res, g_oscratch);
    } else {
        out_res = o;
        out_w   = o + RES_N;
    }

    cudaFuncSetAttribute(fused_attn, cudaFuncAttributeMaxDynamicSharedMemorySize, SMEM_BYTES);
    fused_attn<<<dim3(SSEQ / 128, NHEAD), 256, SMEM_BYTES>>>(Q, K, V, pad, out_w, out_res);
}

// round 11
// speedup vs baseline: 1.5786x; 1.5786x over previous
#include <cuda_runtime.h>
#include <cuda_fp16.h>
#include <cstdint>

#define BB 4
#define HH 16
#define SSEQ 2048
#define DDIM 64
#define NHEAD (BB * HH)
#define STRD 72          // fp16 per SMEM operand row (64 + pad -> conflict-free ldmatrix)
#define UNIF (1.0f / 2048.0f)

// ---------------- mma.sync m16n8k16 fp16 (family-portable, sm_80) ------------
__device__ __forceinline__ void mma_f16(float* c, const uint32_t* a, const uint32_t* b) {
    asm volatile(
        "mma.sync.aligned.m16n8k16.row.col.f32.f16.f16.f32 "
        "{%0,%1,%2,%3}, {%4,%5,%6,%7}, {%8,%9}, {%0,%1,%2,%3};"
        : "+f"(c[0]), "+f"(c[1]), "+f"(c[2]), "+f"(c[3])
        : "r"(a[0]), "r"(a[1]), "r"(a[2]), "r"(a[3]), "r"(b[0]), "r"(b[1]));
}
__device__ __forceinline__ void ldsm4(uint32_t* r, uint32_t addr) {
    asm volatile("ldmatrix.sync.aligned.m8n8.x4.shared.b16 {%0,%1,%2,%3}, [%4];"
                 : "=r"(r[0]), "=r"(r[1]), "=r"(r[2]), "=r"(r[3]) : "r"(addr));
}
__device__ __forceinline__ void ldsm4t(uint32_t* r, uint32_t addr) {
    asm volatile("ldmatrix.sync.aligned.m8n8.x4.trans.shared.b16 {%0,%1,%2,%3}, [%4];"
                 : "=r"(r[0]), "=r"(r[1]), "=r"(r[2]), "=r"(r[3]) : "r"(addr));
}
__device__ __forceinline__ uint32_t smem_u32(const void* p) {
    uint32_t a;
    asm("{ .reg .u64 t; cvta.to.shared.u64 t, %1; cvt.u32.u64 %0, t; }" : "=r"(a) : "l"(p));
    return a;
}
__device__ __forceinline__ uint32_t packh2(float x, float y) {
    __half2 h = __floats2half2_rn(x, y);
    return *(uint32_t*)&h;
}

// scratch for output-variant cases
__device__ float g_wscratch[(size_t)NHEAD * SSEQ * SSEQ];
__device__ float g_oscratch[(size_t)NHEAD * SSEQ * DDIM];

// SMEM layout (bytes)
#define OFF_Q    0
#define OFF_K    (OFF_Q + 128 * STRD * 2)        // 18432
#define OFF_V    (OFF_K + 64 * STRD * 2)         // 27648
#define OFF_SUM  (OFF_V + 64 * STRD * 2)         // 36864
#define OFF_PAD  (OFF_SUM + 128 * 4)             // 37376
#define SMEM_BYTES (OFF_PAD + 64 * 4)            // 37632

// single-pass fp16 QK^T for one 64-col chunk; warp tile 16(m) x 64(n)
__device__ __forceinline__ void qk_1pass(float acc[8][4], uint32_t aBase, uint32_t kBase)
{
    #pragma unroll
    for (int nf = 0; nf < 8; ++nf)
        #pragma unroll
        for (int j = 0; j < 4; ++j) acc[nf][j] = 0.f;

    #pragma unroll
    for (int ks = 0; ks < 4; ++ks) {
        uint32_t a[4];
        ldsm4(a, aBase + ks * 32);
        #pragma unroll
        for (int nfp = 0; nfp < 4; ++nfp) {
            uint32_t b4[4];
            ldsm4(b4, kBase + nfp * (16 * STRD * 2) + ks * 32);
            mma_f16(acc[2 * nfp],     a, b4);
            mma_f16(acc[2 * nfp + 1], a, b4 + 2);
        }
    }
}

__global__ void __launch_bounds__(256, 2)
fused_attn(const float* __restrict__ Q, const float* __restrict__ K,
           const float* __restrict__ V, const int* __restrict__ pad,
           float* __restrict__ W, float* __restrict__ O)
{
    extern __shared__ char smem[];
    const uint32_t sb = smem_u32(smem);
    float* ssum = (float*)(smem + OFF_SUM);
    int*   spad = (int*)(smem + OFF_PAD);

    const int tid = threadIdx.x;
    const int wid = tid >> 5, lane = tid & 31;
    const int g = lane >> 2, tq = lane & 3;
    const int head = blockIdx.y;
    const int q0 = blockIdx.x * 128;
    const int b = head >> 4;
    const int mrow = wid * 16;
    const int r0 = mrow + g, r1 = r0 + 8;
    const int qg0 = q0 + r0, qg1 = q0 + r1;

    // per-thread ldmatrix base addresses (chunk-invariant)
    const uint32_t aBase = sb + OFF_Q +
        (uint32_t)(((mrow + (lane & 15)) * STRD + ((lane >> 4) << 3)) * 2);
    const uint32_t kBase = sb + OFF_K +
        (uint32_t)((((lane & 7) + ((lane & 16) ? 8 : 0)) * STRD + ((lane & 8) ? 8 : 0)) * 2);
    const uint32_t vBase = sb + OFF_V +
        (uint32_t)((((lane & 7) + ((lane & 8) ? 8 : 0)) * STRD + ((lane & 16) ? 8 : 0)) * 2);

    // ---- stage Q once (x0.125, fp16) ----
    const float4* Qg = (const float4*)(Q + ((size_t)head * SSEQ + q0) * DDIM);
    for (int i = tid; i < 128 * 16; i += 256) {
        const int r = i >> 4, c4 = i & 15;
        const float4 v = Qg[i];
        uint32_t* d = (uint32_t*)(smem + OFF_Q + (r * STRD + c4 * 4) * 2);
        d[0] = packh2(v.x * 0.125f, v.y * 0.125f);
        d[1] = packh2(v.z * 0.125f, v.w * 0.125f);
    }
    if (tid < 128) ssum[tid] = 0.f;

    const float4* Kg4 = (const float4*)(K + (size_t)head * SSEQ * DDIM);
    const float4* Vg4 = (const float4*)(V + (size_t)head * SSEQ * DDIM);

    // ================= Phase 1: row sums of exp(s) (no max pass) ===========
    for (int t = 0; t < 32; ++t) {
        const int c0 = t * 64;
        __syncthreads();
        for (int i = tid; i < 64 * 16; i += 256) {
            const int r = i >> 4, c4 = i & 15;
            const float4 k = Kg4[(size_t)c0 * 16 + i];
            uint32_t* d = (uint32_t*)(smem + OFF_K + (r * STRD + c4 * 4) * 2);
            d[0] = packh2(k.x, k.y);
            d[1] = packh2(k.z, k.w);
        }
        if (tid < 64) spad[tid] = pad[b * SSEQ + c0 + tid];
        __syncthreads();

        float acc[8][4];
        qk_1pass(acc, aBase, kBase);

        float rs0 = 0.f, rs1 = 0.f;
        #pragma unroll
        for (int nf = 0; nf < 8; ++nf) {
            const int c = nf * 8 + 2 * tq;
            const int cg = c0 + c;
            const int p0 = spad[c], p1 = spad[c + 1];
            rs0 += (((cg     > qg0 ? 1 : 0) + p0) == 1) ? 0.f : __expf(acc[nf][0]);
            rs0 += (((cg + 1 > qg0 ? 1 : 0) + p1) == 1) ? 0.f : __expf(acc[nf][1]);
            rs1 += (((cg     > qg1 ? 1 : 0) + p0) == 1) ? 0.f : __expf(acc[nf][2]);
            rs1 += (((cg + 1 > qg1 ? 1 : 0) + p1) == 1) ? 0.f : __expf(acc[nf][3]);
        }
        rs0 += __shfl_xor_sync(0xffffffffu, rs0, 1);
        rs0 += __shfl_xor_sync(0xffffffffu, rs0, 2);
        rs1 += __shfl_xor_sync(0xffffffffu, rs1, 1);
        rs1 += __shfl_xor_sync(0xffffffffu, rs1, 2);
        if (tq == 0) { ssum[r0] += rs0; ssum[r1] += rs1; }
    }
    __syncthreads();
    if (tid < 128) {
        const float s = ssum[tid];
        ssum[tid] = (s == 0.f) ? -1.f : 1.f / s;   // -1 sentinel: all-masked row
    }
    __syncthreads();
    const float inv0 = ssum[r0], inv1 = ssum[r1];
    const bool uni0 = inv0 < 0.f, uni1 = inv1 < 0.f;

    // ================= Phase 2: recompute, write W, accumulate O ===========
    float oacc[8][4];
    #pragma unroll
    for (int nf = 0; nf < 8; ++nf)
        #pragma unroll
        for (int j = 0; j < 4; ++j) oacc[nf][j] = 0.f;

    for (int t = 0; t < 32; ++t) {
        const int c0 = t * 64;
        __syncthreads();
        for (int i = tid; i < 64 * 16; i += 256) {
            const int r = i >> 4, c4 = i & 15;
            const float4 k = Kg4[(size_t)c0 * 16 + i];
            uint32_t* d = (uint32_t*)(smem + OFF_K + (r * STRD + c4 * 4) * 2);
            d[0] = packh2(k.x, k.y);
            d[1] = packh2(k.z, k.w);
            const float4 v = Vg4[(size_t)c0 * 16 + i];
            uint32_t* dv = (uint32_t*)(smem + OFF_V + (r * STRD + c4 * 4) * 2);
            dv[0] = packh2(v.x, v.y);
            dv[1] = packh2(v.z, v.w);
        }
        if (tid < 64) spad[tid] = pad[b * SSEQ + c0 + tid];
        __syncthreads();

        float acc[8][4];
        qk_1pass(acc, aBase, kBase);   // bitwise identical to phase 1

        // p = exp(s) * inv (or uniform / 0), write W once
        float* wr0 = W + ((size_t)head * SSEQ + qg0) * SSEQ + c0;
        float* wr1 = W + ((size_t)head * SSEQ + qg1) * SSEQ + c0;
        #pragma unroll
        for (int nf = 0; nf < 8; ++nf) {
            const int c = nf * 8 + 2 * tq;
            const int cg = c0 + c;
            const int p0 = spad[c], p1 = spad[c + 1];
            float v0 = uni0 ? UNIF : ((((cg     > qg0 ? 1 : 0) + p0) == 1) ? 0.f : __expf(acc[nf][0]) * inv0);
            float v1 = uni0 ? UNIF : ((((cg + 1 > qg0 ? 1 : 0) + p1) == 1) ? 0.f : __expf(acc[nf][1]) * inv0);
            float v2 = uni1 ? UNIF : ((((cg     > qg1 ? 1 : 0) + p0) == 1) ? 0.f : __expf(acc[nf][2]) * inv1);
            float v3 = uni1 ? UNIF : ((((cg + 1 > qg1 ? 1 : 0) + p1) == 1) ? 0.f : __expf(acc[nf][3]) * inv1);
            acc[nf][0] = v0; acc[nf][1] = v1; acc[nf][2] = v2; acc[nf][3] = v3;
            __stcs((float2*)(wr0 + c), make_float2(v0, v1));
            __stcs((float2*)(wr1 + c), make_float2(v2, v3));
        }

        // P@V: A straight from p registers; B = V^T fragments via ldmatrix.trans
        #pragma unroll
        for (int j = 0; j < 4; ++j) {
            uint32_t a[4];
            a[0] = packh2(acc[2 * j][0],     acc[2 * j][1]);
            a[1] = packh2(acc[2 * j][2],     acc[2 * j][3]);
            a[2] = packh2(acc[2 * j + 1][0], acc[2 * j + 1][1]);
            a[3] = packh2(acc[2 * j + 1][2], acc[2 * j + 1][3]);
            #pragma unroll
            for (int nfp = 0; nfp < 4; ++nfp) {
                uint32_t b4[4];
                ldsm4t(b4, vBase + j * (16 * STRD * 2) + nfp * 32);
                mma_f16(oacc[2 * nfp],     a, b4);
                mma_f16(oacc[2 * nfp + 1], a, b4 + 2);
            }
        }
    }

    // ---- O epilogue ----
    float* o0 = O + ((size_t)head * SSEQ + qg0) * DDIM;
    float* o1 = O + ((size_t)head * SSEQ + qg1) * DDIM;
    #pragma unroll
    for (int nf = 0; nf < 8; ++nf) {
        const int c = nf * 8 + 2 * tq;
        *(float2*)(o0 + c) = make_float2(oacc[nf][0], oacc[nf][1]);
        *(float2*)(o1 + c) = make_float2(oacc[nf][2], oacc[nf][3]);
    }
}

// ===================== launch =================================================
extern "C" void kernel_launch(void* const* d_in, const int* in_sizes, int n_in,
                              void* d_out, int out_size)
{
    const float* Q   = (const float*)d_in[0];
    const float* K   = (const float*)d_in[1];
    const float* V   = (const float*)d_in[2];
    const int*   pad = (const int*)d_in[3];

    const long long RES_N = (long long)NHEAD * SSEQ * DDIM;
    const long long W_N   = (long long)NHEAD * SSEQ * (long long)SSEQ;

    float* o = (float*)d_out;
    float* out_res = nullptr;
    float* out_w   = nullptr;
    if ((long long)out_size == RES_N) {
        out_res = o;
        cudaGetSymbolAddress((void**)&out_w, g_wscratch);
    } else if ((long long)out_size == W_N) {
        out_w = o;
        cudaGetSymbolAddress((void**)&out_res, g_oscratch);
    } else {
        out_res = o;
        out_w   = o + RES_N;
    }

    cudaFuncSetAttribute(fused_attn, cudaFuncAttributeMaxDynamicSharedMemorySize, SMEM_BYTES);
    fused_attn<<<dim3(SSEQ / 128, NHEAD), 256, SMEM_BYTES>>>(Q, K, V, pad, out_w, out_res);
}

// round 14
// speedup vs baseline: 2.7945x; 1.7703x over previous
#include <cuda_runtime.h>
#include <cuda_fp16.h>
#include <cstdint>

#define BB 4
#define HH 16
#define SSEQ 2048
#define DDIM 64
#define NHEAD (BB * HH)
#define STRD 72          // fp16 per SMEM operand row (64 + pad -> conflict-free ldmatrix)
#define UNIF (1.0f / 2048.0f)

// ---------------- PTX helpers (family-portable, sm_80+) ----------------------
__device__ __forceinline__ void mma_f16(float* c, const uint32_t* a, const uint32_t* b) {
    asm volatile(
        "mma.sync.aligned.m16n8k16.row.col.f32.f16.f16.f32 "
        "{%0,%1,%2,%3}, {%4,%5,%6,%7}, {%8,%9}, {%0,%1,%2,%3};"
        : "+f"(c[0]), "+f"(c[1]), "+f"(c[2]), "+f"(c[3])
        : "r"(a[0]), "r"(a[1]), "r"(a[2]), "r"(a[3]), "r"(b[0]), "r"(b[1]));
}
__device__ __forceinline__ void ldsm4(uint32_t* r, uint32_t addr) {
    asm volatile("ldmatrix.sync.aligned.m8n8.x4.shared.b16 {%0,%1,%2,%3}, [%4];"
                 : "=r"(r[0]), "=r"(r[1]), "=r"(r[2]), "=r"(r[3]) : "r"(addr));
}
__device__ __forceinline__ void ldsm4t(uint32_t* r, uint32_t addr) {
    asm volatile("ldmatrix.sync.aligned.m8n8.x4.trans.shared.b16 {%0,%1,%2,%3}, [%4];"
                 : "=r"(r[0]), "=r"(r[1]), "=r"(r[2]), "=r"(r[3]) : "r"(addr));
}
__device__ __forceinline__ uint32_t smem_u32(const void* p) {
    uint32_t a;
    asm("{ .reg .u64 t; cvta.to.shared.u64 t, %1; cvt.u32.u64 %0, t; }" : "=r"(a) : "l"(p));
    return a;
}
__device__ __forceinline__ uint32_t packh2(float x, float y) {
    __half2 h = __floats2half2_rn(x, y);
    return *(uint32_t*)&h;
}
__device__ __forceinline__ void cp16(uint32_t dst, const void* src) {
    asm volatile("cp.async.cg.shared.global [%0], [%1], 16;" :: "r"(dst), "l"(src));
}
#define CP_COMMIT() asm volatile("cp.async.commit_group;" ::: "memory")
#define CP_WAIT1()  asm volatile("cp.async.wait_group 1;" ::: "memory")

// fp16 copies of inputs (Q pre-scaled by 0.125)
#define N4T (NHEAD * SSEQ * DDIM / 4)    // 2,097,152 float4 groups per tensor
__device__ uint2 g_qh4[N4T];
__device__ uint2 g_kh4[N4T];
__device__ uint2 g_vh4[N4T];

// scratch for output-variant cases
__device__ float g_wscratch[(size_t)NHEAD * SSEQ * SSEQ];
__device__ float g_oscratch[(size_t)NHEAD * SSEQ * DDIM];

// ---------------- pre-convert kernel -----------------------------------------
__global__ void __launch_bounds__(256)
cvt_all(const float4* __restrict__ Q, const float4* __restrict__ K,
        const float4* __restrict__ V)
{
    const int i = blockIdx.x * 256 + threadIdx.x;
    if (i < N4T) {
        const float4 v = Q[i];
        g_qh4[i] = make_uint2(packh2(v.x * 0.125f, v.y * 0.125f),
                              packh2(v.z * 0.125f, v.w * 0.125f));
    } else if (i < 2 * N4T) {
        const int j = i - N4T;
        const float4 v = K[j];
        g_kh4[j] = make_uint2(packh2(v.x, v.y), packh2(v.z, v.w));
    } else {
        const int j = i - 2 * N4T;
        const float4 v = V[j];
        g_vh4[j] = make_uint2(packh2(v.x, v.y), packh2(v.z, v.w));
    }
}

// ---------------- SMEM layout (bytes) ----------------------------------------
#define OFF_Q    0                           // 128 x STRD fp16 = 18432
#define KSTAGE   (64 * STRD * 2)             // 9216
#define OFF_K    (OFF_Q + 128 * STRD * 2)    // 2 stages
#define OFF_V    (OFF_K + 2 * KSTAGE)        // 2 stages
#define OFF_SUM  (OFF_V + 2 * KSTAGE)
#define OFF_PAD  (OFF_SUM + 128 * 4)
#define SMEM_BYTES (OFF_PAD + SSEQ * 4)      // 64128

// single-pass fp16 QK^T for one 64-col chunk; warp tile 16(m) x 64(n)
__device__ __forceinline__ void qk_1pass(float acc[8][4], uint32_t aBase, uint32_t kBase)
{
    #pragma unroll
    for (int nf = 0; nf < 8; ++nf)
        #pragma unroll
        for (int j = 0; j < 4; ++j) acc[nf][j] = 0.f;

    #pragma unroll
    for (int ks = 0; ks < 4; ++ks) {
        uint32_t a[4];
        ldsm4(a, aBase + ks * 32);
        #pragma unroll
        for (int nfp = 0; nfp < 4; ++nfp) {
            uint32_t b4[4];
            ldsm4(b4, kBase + nfp * (16 * STRD * 2) + ks * 32);
            mma_f16(acc[2 * nfp],     a, b4);
            mma_f16(acc[2 * nfp + 1], a, b4 + 2);
        }
    }
}

__global__ void __launch_bounds__(256, 2)
fused_attn(const int* __restrict__ pad, float* __restrict__ W, float* __restrict__ O)
{
    extern __shared__ char smem[];
    const uint32_t sb = smem_u32(smem);
    float* ssum = (float*)(smem + OFF_SUM);
    int*   spad = (int*)(smem + OFF_PAD);

    const int tid = threadIdx.x;
    const int wid = tid >> 5, lane = tid & 31;
    const int tq = lane & 3;
    const int head = blockIdx.y;
    const int q0 = blockIdx.x * 128;
    const int mrow = wid * 16;
    const int r0 = mrow + (lane >> 2), r1 = r0 + 8;
    const int qg0 = q0 + r0, qg1 = q0 + r1;

    const __half* Qh = (const __half*)g_qh4 + ((size_t)head * SSEQ + q0) * DDIM;
    const __half* Kh = (const __half*)g_kh4 + (size_t)head * SSEQ * DDIM;
    const __half* Vh = (const __half*)g_vh4 + (size_t)head * SSEQ * DDIM;

    // per-thread ldmatrix base addresses (chunk-invariant; stage offset added)
    const uint32_t aBase = sb + OFF_Q +
        (uint32_t)(((mrow + (lane & 15)) * STRD + ((lane >> 4) << 3)) * 2);
    const uint32_t kBase = sb + OFF_K +
        (uint32_t)((((lane & 7) + ((lane & 16) ? 8 : 0)) * STRD + ((lane & 8) ? 8 : 0)) * 2);
    const uint32_t vBase = sb + OFF_V +
        (uint32_t)((((lane & 7) + ((lane & 8) ? 8 : 0)) * STRD + ((lane & 16) ? 8 : 0)) * 2);

    // ---- pad mask for the whole row (once) ----
    for (int i = tid; i < SSEQ; i += 256) spad[i] = pad[(head >> 4) * SSEQ + i];

    // ---- async stage Q (4 chunks/thread) + K chunk 0 ----
    {
        #pragma unroll
        for (int j = 0; j < 4; ++j) {
            const int idx = tid + j * 256;            // 1024 x 16B
            const int r = idx >> 3, c16 = idx & 7;
            cp16(sb + OFF_Q + (uint32_t)((r * STRD + c16 * 8) * 2), Qh + r * DDIM + c16 * 8);
        }
        #pragma unroll
        for (int j = 0; j < 2; ++j) {
            const int idx = tid + j * 256;            // 512 x 16B
            const int r = idx >> 3, c16 = idx & 7;
            cp16(sb + OFF_K + (uint32_t)((r * STRD + c16 * 8) * 2), Kh + r * DDIM + c16 * 8);
        }
        CP_COMMIT();
    }

    // ================= Phase 1: row sums of exp(s) =========================
    float rs0 = 0.f, rs1 = 0.f;
    for (int t = 0; t < 32; ++t) {
        const int c0 = t * 64;
        if (t < 31) {
            const uint32_t kd = sb + OFF_K + (uint32_t)(((t + 1) & 1) * KSTAGE);
            const __half* ks = Kh + (size_t)(c0 + 64) * DDIM;
            #pragma unroll
            for (int j = 0; j < 2; ++j) {
                const int idx = tid + j * 256;
                const int r = idx >> 3, c16 = idx & 7;
                cp16(kd + (uint32_t)((r * STRD + c16 * 8) * 2), ks + r * DDIM + c16 * 8);
            }
        }
        CP_COMMIT();
        CP_WAIT1();
        __syncthreads();

        float acc[8][4];
        qk_1pass(acc, aBase, kBase + (uint32_t)((t & 1) * KSTAGE));

        #pragma unroll
        for (int nf = 0; nf < 8; ++nf) {
            const int c = nf * 8 + 2 * tq;
            const int cg = c0 + c;
            const bool p0 = spad[cg] != 0, p1 = spad[cg + 1] != 0;
            rs0 += ((cg     > qg0) != p0) ? 0.f : __expf(acc[nf][0]);
            rs0 += ((cg + 1 > qg0) != p1) ? 0.f : __expf(acc[nf][1]);
            rs1 += ((cg     > qg1) != p0) ? 0.f : __expf(acc[nf][2]);
            rs1 += ((cg + 1 > qg1) != p1) ? 0.f : __expf(acc[nf][3]);
        }
        __syncthreads();   // chunk consumed; next prefetch may overwrite
    }
    rs0 += __shfl_xor_sync(0xffffffffu, rs0, 1);
    rs0 += __shfl_xor_sync(0xffffffffu, rs0, 2);
    rs1 += __shfl_xor_sync(0xffffffffu, rs1, 1);
    rs1 += __shfl_xor_sync(0xffffffffu, rs1, 2);
    if (tq == 0) { ssum[r0] = rs0; ssum[r1] = rs1; }
    __syncthreads();
    if (tid < 128) {
        const float s = ssum[tid];
        ssum[tid] = (s == 0.f) ? -1.f : 1.f / s;   // -1 sentinel: all-masked row
    }

    // prefetch K0+V0 for phase 2 (buffers free: all phase-1 computes done)
    {
        #pragma unroll
        for (int j = 0; j < 2; ++j) {
            const int idx = tid + j * 256;
            const int r = idx >> 3, c16 = idx & 7;
            cp16(sb + OFF_K + (uint32_t)((r * STRD + c16 * 8) * 2), Kh + r * DDIM + c16 * 8);
            cp16(sb + OFF_V + (uint32_t)((r * STRD + c16 * 8) * 2), Vh + r * DDIM + c16 * 8);
        }
        CP_COMMIT();
    }
    __syncthreads();
    const float inv0 = ssum[r0], inv1 = ssum[r1];
    const bool uni0 = inv0 < 0.f, uni1 = inv1 < 0.f;

    // ================= Phase 2: recompute, write W, accumulate O ===========
    float oacc[8][4];
    #pragma unroll
    for (int nf = 0; nf < 8; ++nf)
        #pragma unroll
        for (int j = 0; j < 4; ++j) oacc[nf][j] = 0.f;

    for (int t = 0; t < 32; ++t) {
        const int c0 = t * 64;
        if (t < 31) {
            const uint32_t st = (uint32_t)(((t + 1) & 1) * KSTAGE);
            const __half* ks = Kh + (size_t)(c0 + 64) * DDIM;
            const __half* vs = Vh + (size_t)(c0 + 64) * DDIM;
            #pragma unroll
            for (int j = 0; j < 2; ++j) {
                const int idx = tid + j * 256;
                const int r = idx >> 3, c16 = idx & 7;
                const uint32_t off = (uint32_t)((r * STRD + c16 * 8) * 2);
                cp16(sb + OFF_K + st + off, ks + r * DDIM + c16 * 8);
                cp16(sb + OFF_V + st + off, vs + r * DDIM + c16 * 8);
            }
        }
        CP_COMMIT();
        CP_WAIT1();
        __syncthreads();

        const uint32_t st = (uint32_t)((t & 1) * KSTAGE);
        float acc[8][4];
        qk_1pass(acc, aBase, kBase + st);   // bitwise identical to phase 1

        // p = exp(s) * inv (or uniform / 0), write W once
        float* wr0 = W + ((size_t)head * SSEQ + qg0) * SSEQ + c0;
        float* wr1 = W + ((size_t)head * SSEQ + qg1) * SSEQ + c0;
        #pragma unroll
        for (int nf = 0; nf < 8; ++nf) {
            const int c = nf * 8 + 2 * tq;
            const int cg = c0 + c;
            const bool p0 = spad[cg] != 0, p1 = spad[cg + 1] != 0;
            float v0 = uni0 ? UNIF : (((cg     > qg0) != p0) ? 0.f : __expf(acc[nf][0]) * inv0);
            float v1 = uni0 ? UNIF : (((cg + 1 > qg0) != p1) ? 0.f : __expf(acc[nf][1]) * inv0);
            float v2 = uni1 ? UNIF : (((cg     > qg1) != p0) ? 0.f : __expf(acc[nf][2]) * inv1);
            float v3 = uni1 ? UNIF : (((cg + 1 > qg1) != p1) ? 0.f : __expf(acc[nf][3]) * inv1);
            acc[nf][0] = v0; acc[nf][1] = v1; acc[nf][2] = v2; acc[nf][3] = v3;
            __stcs((float2*)(wr0 + c), make_float2(v0, v1));
            __stcs((float2*)(wr1 + c), make_float2(v2, v3));
        }

        // P@V: A straight from p registers; B = V^T fragments via ldmatrix.trans
        #pragma unroll
        for (int j = 0; j < 4; ++j) {
            uint32_t a[4];
            a[0] = packh2(acc[2 * j][0],     acc[2 * j][1]);
            a[1] = packh2(acc[2 * j][2],     acc[2 * j][3]);
            a[2] = packh2(acc[2 * j + 1][0], acc[2 * j + 1][1]);
            a[3] = packh2(acc[2 * j + 1][2], acc[2 * j + 1][3]);
            #pragma unroll
            for (int nfp = 0; nfp < 4; ++nfp) {
                uint32_t b4[4];
                ldsm4t(b4, vBase + st + j * (16 * STRD * 2) + nfp * 32);
                mma_f16(oacc[2 * nfp],     a, b4);
                mma_f16(oacc[2 * nfp + 1], a, b4 + 2);
            }
        }
        __syncthreads();   // chunk consumed; next prefetch may overwrite
    }

    // ---- O epilogue ----
    float* o0 = O + ((size_t)head * SSEQ + qg0) * DDIM;
    float* o1 = O + ((size_t)head * SSEQ + qg1) * DDIM;
    #pragma unroll
    for (int nf = 0; nf < 8; ++nf) {
        const int c = nf * 8 + 2 * tq;
        *(float2*)(o0 + c) = make_float2(oacc[nf][0], oacc[nf][1]);
        *(float2*)(o1 + c) = make_float2(oacc[nf][2], oacc[nf][3]);
    }
}

// ===================== launch =================================================
extern "C" void kernel_launch(void* const* d_in, const int* in_sizes, int n_in,
                              void* d_out, int out_size)
{
    const float* Q   = (const float*)d_in[0];
    const float* K   = (const float*)d_in[1];
    const float* V   = (const float*)d_in[2];
    const int*   pad = (const int*)d_in[3];

    const long long RES_N = (long long)NHEAD * SSEQ * DDIM;
    const long long W_N   = (long long)NHEAD * SSEQ * (long long)SSEQ;

    float* o = (float*)d_out;
    float* out_res = nullptr;
    float* out_w   = nullptr;
    if ((long long)out_size == RES_N) {
        out_res = o;
        cudaGetSymbolAddress((void**)&out_w, g_wscratch);
    } else if ((long long)out_size == W_N) {
        out_w = o;
        cudaGetSymbolAddress((void**)&out_res, g_oscratch);
    } else {
        out_res = o;
        out_w   = o + RES_N;
    }

    cudaFuncSetAttribute(fused_attn, cudaFuncAttributeMaxDynamicSharedMemorySize, SMEM_BYTES);

    cvt_all<<<3 * N4T / 256, 256>>>((const float4*)Q, (const float4*)K, (const float4*)V);
    fused_attn<<<dim3(SSEQ / 128, NHEAD), 256, SMEM_BYTES>>>(pad, out_w, out_res);
}

// round 16
// speedup vs baseline: 3.2276x; 1.1550x over previous
#include <cuda_runtime.h>
#include <cuda_fp16.h>
#include <cstdint>

#define BB 4
#define HH 16
#define SSEQ 2048
#define DDIM 64
#define NHEAD (BB * HH)
#define STRD 72          // fp16 per SMEM operand row (64 + pad -> conflict-free ldmatrix)
#define UNIF (1.0f / 2048.0f)
#define QSCALE (0.125f * 1.4426950408889634f)   // 1/sqrt(64) * log2(e)

// ---------------- PTX helpers (family-portable, sm_80+) ----------------------
__device__ __forceinline__ void mma_f16(float* c, const uint32_t* a, const uint32_t* b) {
    asm volatile(
        "mma.sync.aligned.m16n8k16.row.col.f32.f16.f16.f32 "
        "{%0,%1,%2,%3}, {%4,%5,%6,%7}, {%8,%9}, {%0,%1,%2,%3};"
        : "+f"(c[0]), "+f"(c[1]), "+f"(c[2]), "+f"(c[3])
        : "r"(a[0]), "r"(a[1]), "r"(a[2]), "r"(a[3]), "r"(b[0]), "r"(b[1]));
}
__device__ __forceinline__ void ldsm4(uint32_t* r, uint32_t addr) {
    asm volatile("ldmatrix.sync.aligned.m8n8.x4.shared.b16 {%0,%1,%2,%3}, [%4];"
                 : "=r"(r[0]), "=r"(r[1]), "=r"(r[2]), "=r"(r[3]) : "r"(addr));
}
__device__ __forceinline__ void ldsm4t(uint32_t* r, uint32_t addr) {
    asm volatile("ldmatrix.sync.aligned.m8n8.x4.trans.shared.b16 {%0,%1,%2,%3}, [%4];"
                 : "=r"(r[0]), "=r"(r[1]), "=r"(r[2]), "=r"(r[3]) : "r"(addr));
}
__device__ __forceinline__ uint32_t smem_u32(const void* p) {
    uint32_t a;
    asm("{ .reg .u64 t; cvta.to.shared.u64 t, %1; cvt.u32.u64 %0, t; }" : "=r"(a) : "l"(p));
    return a;
}
__device__ __forceinline__ uint32_t packh2(float x, float y) {
    __half2 h = __floats2half2_rn(x, y);
    return *(uint32_t*)&h;
}
__device__ __forceinline__ float ex2(float x) {
    float r; asm("ex2.approx.ftz.f32 %0, %1;" : "=f"(r) : "f"(x)); return r;
}
__device__ __forceinline__ void cp16(uint32_t dst, const void* src) {
    asm volatile("cp.async.cg.shared.global [%0], [%1], 16;" :: "r"(dst), "l"(src));
}
#define CP_COMMIT() asm volatile("cp.async.commit_group;" ::: "memory")
#define CP_WAIT2()  asm volatile("cp.async.wait_group 2;" ::: "memory")

// fp16 copies of inputs (Q pre-scaled by 0.125*log2e)
#define N4T (NHEAD * SSEQ * DDIM / 4)
__device__ uint2 g_qh4[N4T];
__device__ uint2 g_kh4[N4T];
__device__ uint2 g_vh4[N4T];

// scratch for output-variant cases
__device__ float g_wscratch[(size_t)NHEAD * SSEQ * SSEQ];
__device__ float g_oscratch[(size_t)NHEAD * SSEQ * DDIM];

// ---------------- pre-convert kernel -----------------------------------------
__global__ void __launch_bounds__(256)
cvt_all(const float4* __restrict__ Q, const float4* __restrict__ K,
        const float4* __restrict__ V)
{
    const int i = blockIdx.x * 256 + threadIdx.x;
    if (i < N4T) {
        const float4 v = Q[i];
        g_qh4[i] = make_uint2(packh2(v.x * QSCALE, v.y * QSCALE),
                              packh2(v.z * QSCALE, v.w * QSCALE));
    } else if (i < 2 * N4T) {
        const int j = i - N4T;
        const float4 v = K[j];
        g_kh4[j] = make_uint2(packh2(v.x, v.y), packh2(v.z, v.w));
    } else {
        const int j = i - 2 * N4T;
        const float4 v = V[j];
        g_vh4[j] = make_uint2(packh2(v.x, v.y), packh2(v.z, v.w));
    }
}

// ---------------- SMEM layout (bytes) ----------------------------------------
#define STG      (64 * STRD * 2)             // 9216 per K or V stage
#define OFF_Q    0                           // 18432
#define OFF_K    (OFF_Q + 128 * STRD * 2)    // 4 stages
#define OFF_V    (OFF_K + 4 * STG)           // 4 stages
#define OFF_SUM  (OFF_V + 4 * STG)           // 128 floats
#define OFF_PB   (OFF_SUM + 128 * 4)         // 64 words of pad bits
#define SMEM_BYTES (OFF_PB + 64 * 4)         // 92928

// single-pass fp16 QK^T for one 64-col chunk; warp tile 16(m) x 64(n)
__device__ __forceinline__ void qk_1pass(float acc[8][4], uint32_t aBase, uint32_t kBase)
{
    #pragma unroll
    for (int nf = 0; nf < 8; ++nf)
        #pragma unroll
        for (int j = 0; j < 4; ++j) acc[nf][j] = 0.f;

    #pragma unroll
    for (int ks = 0; ks < 4; ++ks) {
        uint32_t a[4];
        ldsm4(a, aBase + ks * 32);
        #pragma unroll
        for (int nfp = 0; nfp < 4; ++nfp) {
            uint32_t b4[4];
            ldsm4(b4, kBase + nfp * (16 * STRD * 2) + ks * 32);
            mma_f16(acc[2 * nfp],     a, b4);
            mma_f16(acc[2 * nfp + 1], a, b4 + 2);
        }
    }
}

__global__ void __launch_bounds__(256, 2)
fused_attn(const int* __restrict__ pad, float* __restrict__ W, float* __restrict__ O)
{
    extern __shared__ char smem[];
    const uint32_t sb = smem_u32(smem);
    float*    ssum  = (float*)(smem + OFF_SUM);
    uint32_t* pbits = (uint32_t*)(smem + OFF_PB);

    const int tid = threadIdx.x;
    const int wid = tid >> 5, lane = tid & 31;
    const int tq = lane & 3;
    const int head = blockIdx.y;
    const int q0 = blockIdx.x * 128;
    const int mrow = wid * 16;
    const int r0 = mrow + (lane >> 2), r1 = r0 + 8;
    const int qg0 = q0 + r0, qg1 = q0 + r1;

    const __half* Qh = (const __half*)g_qh4 + ((size_t)head * SSEQ + q0) * DDIM;
    const __half* Kh = (const __half*)g_kh4 + (size_t)head * SSEQ * DDIM;
    const __half* Vh = (const __half*)g_vh4 + (size_t)head * SSEQ * DDIM;

    // per-thread ldmatrix base addresses (chunk-invariant; stage offset added)
    const uint32_t aBase = sb + OFF_Q +
        (uint32_t)(((mrow + (lane & 15)) * STRD + ((lane >> 4) << 3)) * 2);
    const uint32_t kBase = sb + OFF_K +
        (uint32_t)((((lane & 7) + ((lane & 16) ? 8 : 0)) * STRD + ((lane & 8) ? 8 : 0)) * 2);
    const uint32_t vBase = sb + OFF_V +
        (uint32_t)((((lane & 7) + ((lane & 8) ? 8 : 0)) * STRD + ((lane & 16) ? 8 : 0)) * 2);

    // per-thread cp.async slot (row r, 16B chunk c16)
    const int cpr = tid >> 3, cpc = tid & 7;
    const uint32_t cpo = (uint32_t)((cpr * STRD + cpc * 8) * 2);
    const uint32_t cpo2 = (uint32_t)(((cpr + 32) * STRD + cpc * 8) * 2);
    const size_t cpg = (size_t)cpr * DDIM + cpc * 8;
    const size_t cpg2 = (size_t)(cpr + 32) * DDIM + cpc * 8;

    // ---- pack pad mask into bits (ballot) ----
    const int* padb = pad + (head >> 4) * SSEQ;
    #pragma unroll
    for (int k = 0; k < 8; ++k) {
        const unsigned bal = __ballot_sync(0xffffffffu, padb[k * 256 + tid] != 0);
        if (lane == 0) pbits[k * 8 + wid] = bal;
    }

    // ---- prologue: group0 = Q + K stage0; group1 = K stage1 ----
    {
        #pragma unroll
        for (int j = 0; j < 4; ++j) {
            const int idx = tid + j * 256;
            const int r = idx >> 3, c16 = idx & 7;
            cp16(sb + OFF_Q + (uint32_t)((r * STRD + c16 * 8) * 2), Qh + r * DDIM + c16 * 8);
        }
        cp16(sb + OFF_K + cpo,  Kh + cpg);
        cp16(sb + OFF_K + cpo2, Kh + cpg2);
        CP_COMMIT();
        cp16(sb + OFF_K + STG + cpo,  Kh + 64 * DDIM + cpg);
        cp16(sb + OFF_K + STG + cpo2, Kh + 64 * DDIM + cpg2);
        CP_COMMIT();
    }

    // ================= Phase 1: row sums of 2^s ============================
    float rs0 = 0.f, rs1 = 0.f;
    for (int t = 0; t < 32; ++t) {
        if (t + 2 < 32) {
            const uint32_t kd = sb + OFF_K + (uint32_t)(((t + 2) & 3) * STG);
            const __half* ks = Kh + (size_t)(t + 2) * 64 * DDIM;
            cp16(kd + cpo,  ks + cpg);
            cp16(kd + cpo2, ks + cpg2);
        }
        CP_COMMIT();
        CP_WAIT2();
        __syncthreads();

        float acc[8][4];
        qk_1pass(acc, aBase, kBase + (uint32_t)((t & 3) * STG));

        const int c0 = t * 64;
        const uint64_t w = (uint64_t)pbits[c0 >> 5] | ((uint64_t)pbits[(c0 >> 5) + 1] << 32);
        #pragma unroll
        for (int nf = 0; nf < 8; ++nf) {
            const int bp = nf * 8 + 2 * tq;
            const int cg = c0 + bp;
            const bool p0 = (w >> bp) & 1, p1 = (w >> (bp + 1)) & 1;
            rs0 += ((cg     > qg0) == p0) ? ex2(acc[nf][0]) : 0.f;
            rs0 += ((cg + 1 > qg0) == p1) ? ex2(acc[nf][1]) : 0.f;
            rs1 += ((cg     > qg1) == p0) ? ex2(acc[nf][2]) : 0.f;
            rs1 += ((cg + 1 > qg1) == p1) ? ex2(acc[nf][3]) : 0.f;
        }
    }
    rs0 += __shfl_xor_sync(0xffffffffu, rs0, 1);
    rs0 += __shfl_xor_sync(0xffffffffu, rs0, 2);
    rs1 += __shfl_xor_sync(0xffffffffu, rs1, 1);
    rs1 += __shfl_xor_sync(0xffffffffu, rs1, 2);

    // prefetch K0+V0, K1+V1 for phase 2 (stage0/1 buffers idle since t=28/29)
    cp16(sb + OFF_K + cpo,  Kh + cpg);
    cp16(sb + OFF_K + cpo2, Kh + cpg2);
    cp16(sb + OFF_V + cpo,  Vh + cpg);
    cp16(sb + OFF_V + cpo2, Vh + cpg2);
    CP_COMMIT();
    cp16(sb + OFF_K + STG + cpo,  Kh + 64 * DDIM + cpg);
    cp16(sb + OFF_K + STG + cpo2, Kh + 64 * DDIM + cpg2);
    cp16(sb + OFF_V + STG + cpo,  Vh + 64 * DDIM + cpg);
    cp16(sb + OFF_V + STG + cpo2, Vh + 64 * DDIM + cpg2);
    CP_COMMIT();

    if (tq == 0) { ssum[r0] = rs0; ssum[r1] = rs1; }
    __syncthreads();
    const float s0 = ssum[r0], s1 = ssum[r1];
    const bool uni0 = (s0 == 0.f), uni1 = (s1 == 0.f);
    const float inv0 = uni0 ? 0.f : 1.0f / s0;
    const float inv1 = uni1 ? 0.f : 1.0f / s1;

    // ================= Phase 2: recompute, write W, accumulate O ===========
    float oacc[8][4];
    #pragma unroll
    for (int nf = 0; nf < 8; ++nf)
        #pragma unroll
        for (int j = 0; j < 4; ++j) oacc[nf][j] = 0.f;

    for (int t = 0; t < 32; ++t) {
        if (t + 2 < 32) {
            const uint32_t st = (uint32_t)(((t + 2) & 3) * STG);
            const __half* ks = Kh + (size_t)(t + 2) * 64 * DDIM;
            const __half* vs = Vh + (size_t)(t + 2) * 64 * DDIM;
            cp16(sb + OFF_K + st + cpo,  ks + cpg);
            cp16(sb + OFF_K + st + cpo2, ks + cpg2);
            cp16(sb + OFF_V + st + cpo,  vs + cpg);
            cp16(sb + OFF_V + st + cpo2, vs + cpg2);
        }
        CP_COMMIT();
        CP_WAIT2();
        __syncthreads();

        const uint32_t st = (uint32_t)((t & 3) * STG);
        float acc[8][4];
        qk_1pass(acc, aBase, kBase + st);   // bitwise identical to phase 1

        const int c0 = t * 64;
        const uint64_t w = (uint64_t)pbits[c0 >> 5] | ((uint64_t)pbits[(c0 >> 5) + 1] << 32);
        float* wr0 = W + ((size_t)head * SSEQ + qg0) * SSEQ + c0;
        float* wr1 = W + ((size_t)head * SSEQ + qg1) * SSEQ + c0;
        #pragma unroll
        for (int nf = 0; nf < 8; ++nf) {
            const int bp = nf * 8 + 2 * tq;
            const int cg = c0 + bp;
            const bool p0 = (w >> bp) & 1, p1 = (w >> (bp + 1)) & 1;
            float v0 = uni0 ? UNIF : (((cg     > qg0) == p0) ? ex2(acc[nf][0]) * inv0 : 0.f);
            float v1 = uni0 ? UNIF : (((cg + 1 > qg0) == p1) ? ex2(acc[nf][1]) * inv0 : 0.f);
            float v2 = uni1 ? UNIF : (((cg     > qg1) == p0) ? ex2(acc[nf][2]) * inv1 : 0.f);
            float v3 = uni1 ? UNIF : (((cg + 1 > qg1) == p1) ? ex2(acc[nf][3]) * inv1 : 0.f);
            acc[nf][0] = v0; acc[nf][1] = v1; acc[nf][2] = v2; acc[nf][3] = v3;
            __stcs((float2*)(wr0 + bp), make_float2(v0, v1));
            __stcs((float2*)(wr1 + bp), make_float2(v2, v3));
        }

        // P@V: A straight from p registers; B = V^T fragments via ldmatrix.trans
        #pragma unroll
        for (int j = 0; j < 4; ++j) {
            uint32_t a[4];
            a[0] = packh2(acc[2 * j][0],     acc[2 * j][1]);
            a[1] = packh2(acc[2 * j][2],     acc[2 * j][3]);
            a[2] = packh2(acc[2 * j + 1][0], acc[2 * j + 1][1]);
            a[3] = packh2(acc[2 * j + 1][2], acc[2 * j + 1][3]);
            #pragma unroll
            for (int nfp = 0; nfp < 4; ++nfp) {
                uint32_t b4[4];
                ldsm4t(b4, vBase + st + j * (16 * STRD * 2) + nfp * 32);
                mma_f16(oacc[2 * nfp],     a, b4);
                mma_f16(oacc[2 * nfp + 1], a, b4 + 2);
            }
        }
    }

    // ---- O epilogue ----
    float* o0 = O + ((size_t)head * SSEQ + qg0) * DDIM;
    float* o1 = O + ((size_t)head * SSEQ + qg1) * DDIM;
    #pragma unroll
    for (int nf = 0; nf < 8; ++nf) {
        const int c = nf * 8 + 2 * tq;
        *(float2*)(o0 + c) = make_float2(oacc[nf][0], oacc[nf][1]);
        *(float2*)(o1 + c) = make_float2(oacc[nf][2], oacc[nf][3]);
    }
}

// ===================== launch =================================================
extern "C" void kernel_launch(void* const* d_in, const int* in_sizes, int n_in,
                              void* d_out, int out_size)
{
    const float* Q   = (const float*)d_in[0];
    const float* K   = (const float*)d_in[1];
    const float* V   = (const float*)d_in[2];
    const int*   pad = (const int*)d_in[3];

    const long long RES_N = (long long)NHEAD * SSEQ * DDIM;
    const long long W_N   = (long long)NHEAD * SSEQ * (long long)SSEQ;

    float* o = (float*)d_out;
    float* out_res = nullptr;
    float* out_w   = nullptr;
    if ((long long)out_size == RES_N) {
        out_res = o;
        cudaGetSymbolAddress((void**)&out_w, g_wscratch);
    } else if ((long long)out_size == W_N) {
        out_w = o;
        cudaGetSymbolAddress((void**)&out_res, g_oscratch);
    } else {
        out_res = o;
        out_w   = o + RES_N;
    }

    cudaFuncSetAttribute(fused_attn, cudaFuncAttributeMaxDynamicSharedMemorySize, SMEM_BYTES);

    cvt_all<<<3 * N4T / 256, 256>>>((const float4*)Q, (const float4*)K, (const float4*)V);
    fused_attn<<<dim3(SSEQ / 128, NHEAD), 256, SMEM_BYTES>>>(pad, out_w, out_res);
}

// round 17
// speedup vs baseline: 3.2708x; 1.0134x over previous
#include <cuda_runtime.h>
#include <cuda_fp16.h>
#include <cstdint>

#define BB 4
#define HH 16
#define SSEQ 2048
#define DDIM 64
#define NHEAD (BB * HH)
#define STRD 72          // fp16 per SMEM operand row (64 + pad -> conflict-free ldmatrix)
#define UNIF (1.0f / 2048.0f)
#define QSCALE (0.125f * 1.4426950408889634f)   // 1/sqrt(64) * log2(e)

// ---------------- PTX helpers (family-portable, sm_80+) ----------------------
__device__ __forceinline__ void mma_f16(float* c, const uint32_t* a, const uint32_t* b) {
    asm volatile(
        "mma.sync.aligned.m16n8k16.row.col.f32.f16.f16.f32 "
        "{%0,%1,%2,%3}, {%4,%5,%6,%7}, {%8,%9}, {%0,%1,%2,%3};"
        : "+f"(c[0]), "+f"(c[1]), "+f"(c[2]), "+f"(c[3])
        : "r"(a[0]), "r"(a[1]), "r"(a[2]), "r"(a[3]), "r"(b[0]), "r"(b[1]));
}
__device__ __forceinline__ void ldsm4(uint32_t* r, uint32_t addr) {
    asm volatile("ldmatrix.sync.aligned.m8n8.x4.shared.b16 {%0,%1,%2,%3}, [%4];"
                 : "=r"(r[0]), "=r"(r[1]), "=r"(r[2]), "=r"(r[3]) : "r"(addr));
}
__device__ __forceinline__ void ldsm4t(uint32_t* r, uint32_t addr) {
    asm volatile("ldmatrix.sync.aligned.m8n8.x4.trans.shared.b16 {%0,%1,%2,%3}, [%4];"
                 : "=r"(r[0]), "=r"(r[1]), "=r"(r[2]), "=r"(r[3]) : "r"(addr));
}
__device__ __forceinline__ uint32_t smem_u32(const void* p) {
    uint32_t a;
    asm("{ .reg .u64 t; cvta.to.shared.u64 t, %1; cvt.u32.u64 %0, t; }" : "=r"(a) : "l"(p));
    return a;
}
__device__ __forceinline__ uint32_t packh2(float x, float y) {
    __half2 h = __floats2half2_rn(x, y);
    return *(uint32_t*)&h;
}
__device__ __forceinline__ float ex2(float x) {
    float r; asm("ex2.approx.ftz.f32 %0, %1;" : "=f"(r) : "f"(x)); return r;
}
__device__ __forceinline__ void cp16(uint32_t dst, const void* src) {
    asm volatile("cp.async.cg.shared.global [%0], [%1], 16;" :: "r"(dst), "l"(src));
}
#define CP_COMMIT() asm volatile("cp.async.commit_group;" ::: "memory")
#define CP_WAIT0()  asm volatile("cp.async.wait_group 0;" ::: "memory")

// fp16 copies of inputs (Q pre-scaled by 0.125*log2e)
#define N4T (NHEAD * SSEQ * DDIM / 4)
__device__ uint2 g_qh4[N4T];
__device__ uint2 g_kh4[N4T];
__device__ uint2 g_vh4[N4T];

// scratch for output-variant cases
__device__ float g_wscratch[(size_t)NHEAD * SSEQ * SSEQ];
__device__ float g_oscratch[(size_t)NHEAD * SSEQ * DDIM];

// ---------------- pre-convert kernel -----------------------------------------
__global__ void __launch_bounds__(256)
cvt_all(const float4* __restrict__ Q, const float4* __restrict__ K,
        const float4* __restrict__ V)
{
    const int i = blockIdx.x * 256 + threadIdx.x;
    if (i < N4T) {
        const float4 v = Q[i];
        g_qh4[i] = make_uint2(packh2(v.x * QSCALE, v.y * QSCALE),
                              packh2(v.z * QSCALE, v.w * QSCALE));
    } else if (i < 2 * N4T) {
        const int j = i - N4T;
        const float4 v = K[j];
        g_kh4[j] = make_uint2(packh2(v.x, v.y), packh2(v.z, v.w));
    } else {
        const int j = i - 2 * N4T;
        const float4 v = V[j];
        g_vh4[j] = make_uint2(packh2(v.x, v.y), packh2(v.z, v.w));
    }
}

// ---------------- SMEM layout (bytes) ----------------------------------------
#define STG      (64 * STRD * 2)             // 9216 per K or V stage
#define OFF_Q    0                           // 18432
#define OFF_K    (OFF_Q + 128 * STRD * 2)    // 4 stages
#define OFF_V    (OFF_K + 4 * STG)           // 4 stages
#define OFF_SUM  (OFF_V + 4 * STG)           // 128 floats
#define OFF_PB   (OFF_SUM + 128 * 4)         // 64 words of pad bits
#define SMEM_BYTES (OFF_PB + 64 * 4)         // 92928

// single-pass fp16 QK^T for one 64-col chunk; warp tile 16(m) x 64(n)
__device__ __forceinline__ void qk_1pass(float acc[8][4], uint32_t aBase, uint32_t kBase)
{
    #pragma unroll
    for (int nf = 0; nf < 8; ++nf)
        #pragma unroll
        for (int j = 0; j < 4; ++j) acc[nf][j] = 0.f;

    #pragma unroll
    for (int ks = 0; ks < 4; ++ks) {
        uint32_t a[4];
        ldsm4(a, aBase + ks * 32);
        #pragma unroll
        for (int nfp = 0; nfp < 4; ++nfp) {
            uint32_t b4[4];
            ldsm4(b4, kBase + nfp * (16 * STRD * 2) + ks * 32);
            mma_f16(acc[2 * nfp],     a, b4);
            mma_f16(acc[2 * nfp + 1], a, b4 + 2);
        }
    }
}

__global__ void __launch_bounds__(256, 2)
fused_attn(const int* __restrict__ pad, float* __restrict__ W, float* __restrict__ O)
{
    extern __shared__ char smem[];
    const uint32_t sb = smem_u32(smem);
    float*    ssum  = (float*)(smem + OFF_SUM);
    uint32_t* pbits = (uint32_t*)(smem + OFF_PB);

    const int tid = threadIdx.x;
    const int wid = tid >> 5, lane = tid & 31;
    const int tq = lane & 3;
    const int head = blockIdx.y;
    const int q0 = blockIdx.x * 128;
    const int mrow = wid * 16;
    const int r0 = mrow + (lane >> 2), r1 = r0 + 8;
    const int qg0 = q0 + r0, qg1 = q0 + r1;

    const __half* Qh = (const __half*)g_qh4 + ((size_t)head * SSEQ + q0) * DDIM;
    const __half* Kh = (const __half*)g_kh4 + (size_t)head * SSEQ * DDIM;
    const __half* Vh = (const __half*)g_vh4 + (size_t)head * SSEQ * DDIM;

    // per-thread ldmatrix base addresses (chunk-invariant; stage offset added)
    const uint32_t aBase = sb + OFF_Q +
        (uint32_t)(((mrow + (lane & 15)) * STRD + ((lane >> 4) << 3)) * 2);
    const uint32_t kBase = sb + OFF_K +
        (uint32_t)((((lane & 7) + ((lane & 16) ? 8 : 0)) * STRD + ((lane & 8) ? 8 : 0)) * 2);
    const uint32_t vBase = sb + OFF_V +
        (uint32_t)((((lane & 7) + ((lane & 8) ? 8 : 0)) * STRD + ((lane & 16) ? 8 : 0)) * 2);

    // per-thread cp.async slot (row r, 16B chunk c16)
    const int cpr = tid >> 3, cpc = tid & 7;
    const uint32_t cpo = (uint32_t)((cpr * STRD + cpc * 8) * 2);
    const uint32_t cpo2 = (uint32_t)(((cpr + 32) * STRD + cpc * 8) * 2);
    const size_t cpg = (size_t)cpr * DDIM + cpc * 8;
    const size_t cpg2 = (size_t)(cpr + 32) * DDIM + cpc * 8;

    // ---- pack pad mask into bits (ballot) ----
    const int* padb = pad + (head >> 4) * SSEQ;
    #pragma unroll
    for (int k = 0; k < 8; ++k) {
        const unsigned bal = __ballot_sync(0xffffffffu, padb[k * 256 + tid] != 0);
        if (lane == 0) pbits[k * 8 + wid] = bal;
    }

    // ---- prologue: Q + K stages 0,1 in one group ----
    {
        #pragma unroll
        for (int j = 0; j < 4; ++j) {
            const int idx = tid + j * 256;
            const int r = idx >> 3, c16 = idx & 7;
            cp16(sb + OFF_Q + (uint32_t)((r * STRD + c16 * 8) * 2), Qh + r * DDIM + c16 * 8);
        }
        cp16(sb + OFF_K + cpo,        Kh + cpg);
        cp16(sb + OFF_K + cpo2,       Kh + cpg2);
        cp16(sb + OFF_K + STG + cpo,  Kh + 64 * DDIM + cpg);
        cp16(sb + OFF_K + STG + cpo2, Kh + 64 * DDIM + cpg2);
        CP_COMMIT();
    }

    // ================= Phase 1: row sums of 2^s (16 epochs x 128 cols) ======
    float rs0 = 0.f, rs1 = 0.f;
    for (int e = 0; e < 16; ++e) {
        CP_WAIT0();
        __syncthreads();
        if (e < 15) {   // prefetch next epoch's K pair (slots last read 1 epoch ago)
            const uint32_t sA = (uint32_t)(((2 * e + 2) & 3) * STG);
            const uint32_t sB = (uint32_t)(((2 * e + 3) & 3) * STG);
            const __half* ka = Kh + (size_t)(2 * e + 2) * 64 * DDIM;
            const __half* kb = Kh + (size_t)(2 * e + 3) * 64 * DDIM;
            cp16(sb + OFF_K + sA + cpo,  ka + cpg);
            cp16(sb + OFF_K + sA + cpo2, ka + cpg2);
            cp16(sb + OFF_K + sB + cpo,  kb + cpg);
            cp16(sb + OFF_K + sB + cpo2, kb + cpg2);
            CP_COMMIT();
        } else {        // prefetch phase-2 K0,V0,K1,V1 into slots 0,1
            cp16(sb + OFF_K + cpo,        Kh + cpg);
            cp16(sb + OFF_K + cpo2,       Kh + cpg2);
            cp16(sb + OFF_K + STG + cpo,  Kh + 64 * DDIM + cpg);
            cp16(sb + OFF_K + STG + cpo2, Kh + 64 * DDIM + cpg2);
            cp16(sb + OFF_V + cpo,        Vh + cpg);
            cp16(sb + OFF_V + cpo2,       Vh + cpg2);
            cp16(sb + OFF_V + STG + cpo,  Vh + 64 * DDIM + cpg);
            cp16(sb + OFF_V + STG + cpo2, Vh + 64 * DDIM + cpg2);
            CP_COMMIT();
        }

        #pragma unroll
        for (int h = 0; h < 2; ++h) {
            const int t = 2 * e + h;
            const int c0 = t * 64;
            float acc[8][4];
            qk_1pass(acc, aBase, kBase + (uint32_t)((t & 3) * STG));

            const uint32_t lo = pbits[2 * t], hi = pbits[2 * t + 1];
            #pragma unroll
            for (int nf = 0; nf < 8; ++nf) {
                const int sh = (nf & 3) * 8 + 2 * tq;
                const uint32_t wsel = (nf < 4) ? lo : hi;
                const int cg = c0 + nf * 8 + 2 * tq;
                const bool p0 = (wsel >> sh) & 1, p1 = (wsel >> (sh + 1)) & 1;
                rs0 += ((cg     > qg0) == p0) ? ex2(acc[nf][0]) : 0.f;
                rs0 += ((cg + 1 > qg0) == p1) ? ex2(acc[nf][1]) : 0.f;
                rs1 += ((cg     > qg1) == p0) ? ex2(acc[nf][2]) : 0.f;
                rs1 += ((cg + 1 > qg1) == p1) ? ex2(acc[nf][3]) : 0.f;
            }
        }
    }
    rs0 += __shfl_xor_sync(0xffffffffu, rs0, 1);
    rs0 += __shfl_xor_sync(0xffffffffu, rs0, 2);
    rs1 += __shfl_xor_sync(0xffffffffu, rs1, 1);
    rs1 += __shfl_xor_sync(0xffffffffu, rs1, 2);
    if (tq == 0) { ssum[r0] = rs0; ssum[r1] = rs1; }
    __syncthreads();
    const float s0 = ssum[r0], s1 = ssum[r1];
    const bool uni0 = (s0 == 0.f), uni1 = (s1 == 0.f);
    const float lg0 = uni0 ? 0.f : -__log2f(s0);   // fold 1/sum into exponent
    const float lg1 = uni1 ? 0.f : -__log2f(s1);
    const bool anyuni = __any_sync(0xffffffffu, uni0 || uni1);

    // ================= Phase 2: recompute, write W, accumulate O ===========
    float oacc[8][4];
    #pragma unroll
    for (int nf = 0; nf < 8; ++nf)
        #pragma unroll
        for (int j = 0; j < 4; ++j) oacc[nf][j] = 0.f;

    float* const wbase0 = W + ((size_t)head * SSEQ + qg0) * SSEQ;
    float* const wbase1 = W + ((size_t)head * SSEQ + qg1) * SSEQ;

    for (int e = 0; e < 16; ++e) {
        CP_WAIT0();
        __syncthreads();
        if (e < 15) {
            const uint32_t sA = (uint32_t)(((2 * e + 2) & 3) * STG);
            const uint32_t sB = (uint32_t)(((2 * e + 3) & 3) * STG);
            const __half* ka = Kh + (size_t)(2 * e + 2) * 64 * DDIM;
            const __half* kb = Kh + (size_t)(2 * e + 3) * 64 * DDIM;
            const __half* va = Vh + (size_t)(2 * e + 2) * 64 * DDIM;
            const __half* vb = Vh + (size_t)(2 * e + 3) * 64 * DDIM;
            cp16(sb + OFF_K + sA + cpo,  ka + cpg);
            cp16(sb + OFF_K + sA + cpo2, ka + cpg2);
            cp16(sb + OFF_K + sB + cpo,  kb + cpg);
            cp16(sb + OFF_K + sB + cpo2, kb + cpg2);
            cp16(sb + OFF_V + sA + cpo,  va + cpg);
            cp16(sb + OFF_V + sA + cpo2, va + cpg2);
            cp16(sb + OFF_V + sB + cpo,  vb + cpg);
            cp16(sb + OFF_V + sB + cpo2, vb + cpg2);
            CP_COMMIT();
        }

        #pragma unroll
        for (int h = 0; h < 2; ++h) {
            const int t = 2 * e + h;
            const int c0 = t * 64;
            const uint32_t st = (uint32_t)((t & 3) * STG);
            float acc[8][4];
            qk_1pass(acc, aBase, kBase + st);   // bitwise identical to phase 1

            const uint32_t lo = pbits[2 * t], hi = pbits[2 * t + 1];
            float* wr0 = wbase0 + c0;
            float* wr1 = wbase1 + c0;
            if (!anyuni) {   // fast path: p = 2^(s - log2 sum) or 0
                #pragma unroll
                for (int nf = 0; nf < 8; ++nf) {
                    const int sh = (nf & 3) * 8 + 2 * tq;
                    const uint32_t wsel = (nf < 4) ? lo : hi;
                    const int bp = nf * 8 + 2 * tq;
                    const int cg = c0 + bp;
                    const bool p0 = (wsel >> sh) & 1, p1 = (wsel >> (sh + 1)) & 1;
                    const float v0 = ((cg     > qg0) == p0) ? ex2(acc[nf][0] + lg0) : 0.f;
                    const float v1 = ((cg + 1 > qg0) == p1) ? ex2(acc[nf][1] + lg0) : 0.f;
                    const float v2 = ((cg     > qg1) == p0) ? ex2(acc[nf][2] + lg1) : 0.f;
                    const float v3 = ((cg + 1 > qg1) == p1) ? ex2(acc[nf][3] + lg1) : 0.f;
                    acc[nf][0] = v0; acc[nf][1] = v1; acc[nf][2] = v2; acc[nf][3] = v3;
                    __stcs((float2*)(wr0 + bp), make_float2(v0, v1));
                    __stcs((float2*)(wr1 + bp), make_float2(v2, v3));
                }
            } else {         // rare: some all-masked row -> uniform 1/S
                #pragma unroll
                for (int nf = 0; nf < 8; ++nf) {
                    const int sh = (nf & 3) * 8 + 2 * tq;
                    const uint32_t wsel = (nf < 4) ? lo : hi;
                    const int bp = nf * 8 + 2 * tq;
                    const int cg = c0 + bp;
                    const bool p0 = (wsel >> sh) & 1, p1 = (wsel >> (sh + 1)) & 1;
                    float v0 = uni0 ? UNIF : (((cg     > qg0) == p0) ? ex2(acc[nf][0] + lg0) : 0.f);
                    float v1 = uni0 ? UNIF : (((cg + 1 > qg0) == p1) ? ex2(acc[nf][1] + lg0) : 0.f);
                    float v2 = uni1 ? UNIF : (((cg     > qg1) == p0) ? ex2(acc[nf][2] + lg1) : 0.f);
                    float v3 = uni1 ? UNIF : (((cg + 1 > qg1) == p1) ? ex2(acc[nf][3] + lg1) : 0.f);
                    acc[nf][0] = v0; acc[nf][1] = v1; acc[nf][2] = v2; acc[nf][3] = v3;
                    __stcs((float2*)(wr0 + bp), make_float2(v0, v1));
                    __stcs((float2*)(wr1 + bp), make_float2(v2, v3));
                }
            }

            // P@V: A straight from p registers; B = V^T fragments via ldmatrix.trans
            #pragma unroll
            for (int j = 0; j < 4; ++j) {
                uint32_t a[4];
                a[0] = packh2(acc[2 * j][0],     acc[2 * j][1]);
                a[1] = packh2(acc[2 * j][2],     acc[2 * j][3]);
                a[2] = packh2(acc[2 * j + 1][0], acc[2 * j + 1][1]);
                a[3] = packh2(acc[2 * j + 1][2], acc[2 * j + 1][3]);
                #pragma unroll
                for (int nfp = 0; nfp < 4; ++nfp) {
                    uint32_t b4[4];
                    ldsm4t(b4, vBase + st + j * (16 * STRD * 2) + nfp * 32);
                    mma_f16(oacc[2 * nfp],     a, b4);
                    mma_f16(oacc[2 * nfp + 1], a, b4 + 2);
                }
            }
        }
    }

    // ---- O epilogue ----
    float* o0 = O + ((size_t)head * SSEQ + qg0) * DDIM;
    float* o1 = O + ((size_t)head * SSEQ + qg1) * DDIM;
    #pragma unroll
    for (int nf = 0; nf < 8; ++nf) {
        const int c = nf * 8 + 2 * tq;
        *(float2*)(o0 + c) = make_float2(oacc[nf][0], oacc[nf][1]);
        *(float2*)(o1 + c) = make_float2(oacc[nf][2], oacc[nf][3]);
    }
}

// ===================== launch =================================================
extern "C" void kernel_launch(void* const* d_in, const int* in_sizes, int n_in,
                              void* d_out, int out_size)
{
    const float* Q   = (const float*)d_in[0];
    const float* K   = (const float*)d_in[1];
    const float* V   = (const float*)d_in[2];
    const int*   pad = (const int*)d_in[3];

    const long long RES_N = (long long)NHEAD * SSEQ * DDIM;
    const long long W_N   = (long long)NHEAD * SSEQ * (long long)SSEQ;

    float* o = (float*)d_out;
    float* out_res = nullptr;
    float* out_w   = nullptr;
    if ((long long)out_size == RES_N) {
        out_res = o;
        cudaGetSymbolAddress((void**)&out_w, g_wscratch);
    } else if ((long long)out_size == W_N) {
        out_w = o;
        cudaGetSymbolAddress((void**)&out_res, g_oscratch);
    } else {
        out_res = o;
        out_w   = o + RES_N;
    }

    cudaFuncSetAttribute(fused_attn, cudaFuncAttributeMaxDynamicSharedMemorySize, SMEM_BYTES);

    cvt_all<<<3 * N4T / 256, 256>>>((const float4*)Q, (const float4*)K, (const float4*)V);
    fused_attn<<<dim3(SSEQ / 128, NHEAD), 256, SMEM_BYTES>>>(pad, out_w, out_res);
}